// round 12
// baseline (speedup 1.0000x reference)
#include <cuda_runtime.h>
#include <cuda_fp16.h>
#include <cstdint>

#define NV 10000
#define NC 100000
#define B  256
#define NGROUPS (NC / 8)             // 12500 groups of 8 clauses (24 rows)
#define GRID_MAIN 592                // 148 SMs * 4 blocks (49KB smem each)
#define GRID_PREP 2048
#define STAGES 4
#define ROWS_PER_G 24
#define GBYTES (ROWS_PER_G * 512)    // 12288 B per group
#define SMEM_BYTES (STAGES * GBYTES + STAGES * 8)

// Dual table: row (v,neg) at byte v*1024 + neg*512; each row 512 B = 256 fp16.
// 10.24 MB, L2-resident. Both variants rounded directly from fp32 ->
// every literal value carries rel err <= 2^-11 regardless of negation.
__device__ __align__(16) __half2 g_tab[2 * NV * (B / 2)];
// Per literal: half2-index of its table row: (2v+neg)*128. 1.2 MB.
__device__ __align__(16) unsigned int g_off[NC * 3];

__global__ void __launch_bounds__(256)
prep_k(const float* __restrict__ input,
       const unsigned int* __restrict__ idx_raw,
       const unsigned int* __restrict__ neg_raw,
       unsigned int* __restrict__ out) {
    __shared__ int s_is64;
    const int tid = threadIdx.x;

    // dtype probe: int64 data (small non-negative) -> odd 32-bit words all 0;
    // int32 data -> odd words are random indices, all-zero ~impossible.
    if (tid < 32) {
        unsigned int acc = 0;
        #pragma unroll
        for (int k = 0; k < 4; ++k) acc |= idx_raw[2 * (tid + 32 * k) + 1];
        acc = __reduce_or_sync(0xFFFFFFFFu, acc);
        if (tid == 0) s_is64 = (acc == 0) ? 1 : 0;
    }
    __syncthreads();
    const int stride = s_is64 ? 2 : 1;

    const int gtid = blockIdx.x * 256 + tid;
    const int gsz  = GRID_PREP * 256;

    if (gtid < B) out[gtid] = 0x7F800000u;   // +inf (d_out poisoned each replay)

    for (int i = gtid; i < NC * 3; i += gsz) {
        unsigned int v = idx_raw[i * stride];
        unsigned int n = neg_raw[i * stride] & 1u;
        if (v >= NV) v = NV - 1;              // defensive clamp: no OOB ever
        g_off[i] = v * 256u + n * 128u;
    }

    for (int i = gtid; i < NV * (B / 2); i += gsz) {
        int v = i >> 7;
        int j = i & 127;
        float2 x = ((const float2*)input)[i];
        g_tab[v * 256 + j]       = __floats2half2_rn(x.x, x.y);
        g_tab[v * 256 + 128 + j] = __floats2half2_rn(1.0f - x.x, 1.0f - x.y);
    }
}

__device__ __forceinline__ void mbar_init(uint32_t mbar, uint32_t cnt) {
    asm volatile("mbarrier.init.shared.b64 [%0], %1;" :: "r"(mbar), "r"(cnt) : "memory");
}
__device__ __forceinline__ void mbar_expect_tx(uint32_t mbar, uint32_t bytes) {
    asm volatile("mbarrier.arrive.expect_tx.shared.b64 _, [%0], %1;"
                 :: "r"(mbar), "r"(bytes) : "memory");
}
__device__ __forceinline__ void mbar_wait(uint32_t mbar, uint32_t parity) {
    asm volatile(
        "{\n\t.reg .pred P;\n\t"
        "W%=:\n\t"
        "mbarrier.try_wait.parity.acquire.cta.shared::cta.b64 P, [%0], %1, 0x989680;\n\t"
        "@P bra D%=;\n\t"
        "bra W%=;\n\t"
        "D%=:\n\t}"
        :: "r"(mbar), "r"(parity) : "memory");
}
__device__ __forceinline__ void bulk_cp(uint32_t dst, const void* src, uint32_t mbar) {
    asm volatile(
        "cp.async.bulk.shared::cluster.global.mbarrier::complete_tx::bytes [%0], [%1], 512, [%2];"
        :: "r"(dst), "l"(src), "r"(mbar) : "memory");
}

// Async bulk-copy pipeline: each group = 8 clauses = 24 rows of 512 B.
// Warp 0 lanes 0..23 each issue ONE cp.async.bulk for one row (indices read
// coalesced); lane 0 posts expect_tx(12288). 4 stages -> ~3 groups (36 KB)
// in flight per block, registers uninvolved. All 128 threads consume via
// conflict-free LDS.32 once the stage's mbarrier flips.
__global__ void __launch_bounds__(128)
cnf_k(unsigned int* __restrict__ out) {
    extern __shared__ __align__(1024) unsigned char smem[];
    unsigned char* sdata = smem;
    const uint32_t sbase = (uint32_t)__cvta_generic_to_shared(smem);
    const uint32_t mbase = sbase + STAGES * GBYTES;

    const int t    = threadIdx.x;
    const int w    = t >> 5;
    const int lane = t & 31;
    const int b    = blockIdx.x;
    const int nj   = (NGROUPS - b + GRID_MAIN - 1) / GRID_MAIN;   // local groups

    if (t == 0) {
        #pragma unroll
        for (int s = 0; s < STAGES; ++s) mbar_init(mbase + s * 8, 1);
    }
    __syncthreads();

    auto issue = [&](int j) {   // local group j -> global group b + j*GRID_MAIN
        if (w == 0) {
            const int s = j & (STAGES - 1);
            const uint32_t mb = mbase + s * 8;
            if (lane == 0) mbar_expect_tx(mb, GBYTES);
            if (lane < ROWS_PER_G) {
                int gj = b + j * GRID_MAIN;
                unsigned int off = __ldg(&g_off[gj * ROWS_PER_G + lane]);
                const char* src = (const char*)g_tab + (size_t)off * 4;   // 512B-aligned
                bulk_cp(sbase + s * GBYTES + lane * 512, src, mb);
            }
        }
    };

    const int npro = nj < STAGES ? nj : STAGES;
    for (int j = 0; j < npro; ++j) issue(j);

    __half2 m = __halves2half2(__ushort_as_half(0x7C00), __ushort_as_half(0x7C00)); // +inf

    for (int j = 0; j < nj; ++j) {
        const int s = j & (STAGES - 1);
        mbar_wait(mbase + s * 8, (j >> 2) & 1);

        // row r occupies 128 half2 at sdata + s*GBYTES + r*512;
        // thread t takes half2 column t (batch elems 2t,2t+1): warp reads
        // 128 contiguous bytes -> conflict-free.
        const __half2* rows = (const __half2*)(sdata + s * GBYTES);
        #pragma unroll
        for (int k = 0; k < 8; ++k) {
            __half2 c = __hmax2(__hmax2(rows[(3 * k + 0) * 128 + t],
                                        rows[(3 * k + 1) * 128 + t]),
                                        rows[(3 * k + 2) * 128 + t]);
            m = __hmin2(m, c);
        }

        __syncthreads();                 // all reads of stage s done
        if (j + STAGES < nj) issue(j + STAGES);
    }

    // uint bit order == float order for non-negative floats
    atomicMin(&out[2 * t + 0], __float_as_uint(__low2float(m)));
    atomicMin(&out[2 * t + 1], __float_as_uint(__high2float(m)));
}

extern "C" void kernel_launch(void* const* d_in, const int* in_sizes, int n_in,
                              void* d_out, int out_size) {
    const float*        input   = (const float*)d_in[0];
    const unsigned int* idx_raw = (const unsigned int*)d_in[1];
    const unsigned int* neg_raw = (const unsigned int*)d_in[2];
    unsigned int*       out     = (unsigned int*)d_out;

    cudaFuncSetAttribute(cnf_k, cudaFuncAttributeMaxDynamicSharedMemorySize, SMEM_BYTES);

    prep_k<<<GRID_PREP, 256>>>(input, idx_raw, neg_raw, out);
    cnf_k<<<GRID_MAIN, 128, SMEM_BYTES>>>(out);
}